// round 1
// baseline (speedup 1.0000x reference)
#include <cuda_runtime.h>

#define HH 1025
#define WW 1024
#define NIMG 4            // B*C = 2*2
#define TH 16
#define TW 32
#define RAD 15            // (31-1)/2
#define TILE_H (TH + 2*RAD)   // 46
#define TILE_W (TW + 2*RAD)   // 62
#define SSTRIDE TILE_W

__device__ __forceinline__ void cas(float &x, float &y) {
    float lo = fminf(x, y);
    float hi = fmaxf(x, y);
    x = lo; y = hi;
}

// Exact median of 31 values read at p[0], p[STRIDE], ..., p[30*STRIDE]
// via forgetful selection: working set of 17, each step expels one min
// instance and one max instance (both provably not the median), inserts
// the next value. Fully unrolled compare-exchange (FMNMX) code.
template<int STRIDE>
__device__ __forceinline__ float median31(const float* __restrict__ p) {
    float a[17];
#pragma unroll
    for (int i = 0; i < 17; ++i) a[i] = p[i * STRIDE];
#pragma unroll
    for (int t = 0; t < 14; ++t) {
        const int s = 17 - t;          // current working-set size (17..4)
        // pairwise CAS: mins land on even slots, maxes on odd slots
#pragma unroll
        for (int i = 0; i + 1 < s; i += 2) cas(a[i], a[i + 1]);
        // collect a global-min instance into a[0] (even slots + unpaired tail)
#pragma unroll
        for (int i = 2; i < s; i += 2) cas(a[0], a[i]);
        // collect a global-max instance into a[s-1] (odd slots)
#pragma unroll
        for (int i = 1; i < s - 1; i += 2) cas(a[i], a[s - 1]);
        // discard max (shrink), replace min with next window value
        a[0] = p[(17 + t) * STRIDE];
    }
    // 3 values remain; median is the middle one
    cas(a[0], a[1]); cas(a[1], a[2]); cas(a[0], a[1]);
    return a[1];
}

__global__ __launch_bounds__(TH * TW)
void hpss_kernel(const float* __restrict__ S, float* __restrict__ out, int n) {
    __shared__ float tile[TILE_H * SSTRIDE];

    const int img = blockIdx.z;
    const int h0  = blockIdx.y * TH;
    const int w0  = blockIdx.x * TW;
    const float* __restrict__ Simg = S + (size_t)img * HH * WW;

    // cooperative load of (TH+30)x(TW+30) tile with zero padding
    const int tid      = threadIdx.y * TW + threadIdx.x;
    const int nthreads = TH * TW;
    for (int i = tid; i < TILE_H * TILE_W; i += nthreads) {
        const int r = i / TILE_W;
        const int c = i - r * TILE_W;
        const int gh = h0 - RAD + r;
        const int gw = w0 - RAD + c;
        float v = 0.0f;
        if (gh >= 0 && gh < HH && gw >= 0 && gw < WW)
            v = Simg[gh * WW + gw];
        tile[r * SSTRIDE + c] = v;
    }
    __syncthreads();

    const int h = h0 + threadIdx.y;
    if (h >= HH) return;
    const int w = w0 + threadIdx.x;

    // time-direction median (along W): stride 1 in shared
    const float* rowp = &tile[(threadIdx.y + RAD) * SSTRIDE + threadIdx.x];
    // freq-direction median (along H): stride SSTRIDE in shared
    const float* colp = &tile[threadIdx.y * SSTRIDE + threadIdx.x + RAD];

    const float harm = median31<1>(rowp);
    const float perc = median31<SSTRIDE>(colp);
    const float sv   = tile[(threadIdx.y + RAD) * SSTRIDE + threadIdx.x + RAD];

    // softmask with POWER=2, MARGIN=1: Z cancels exactly ->
    // mask_harm = harm^2/(harm^2+perc^2), mask_perc = perc^2/(...)
    const float h2 = harm * harm;
    const float p2 = perc * perc;
    const float inv = __fdividef(1.0f, h2 + p2);

    const size_t idx = (size_t)img * HH * WW + (size_t)h * WW + w;
    out[idx]             = sv * (h2 * inv);   // harmonic component
    out[(size_t)n + idx] = sv * (p2 * inv);   // percussive component
}

extern "C" void kernel_launch(void* const* d_in, const int* in_sizes, int n_in,
                              void* d_out, int out_size) {
    const float* S = (const float*)d_in[0];
    float* out = (float*)d_out;
    const int n = in_sizes[0];   // 4,198,400 elements; out_size = 2n

    dim3 block(TW, TH);
    dim3 grid(WW / TW, (HH + TH - 1) / TH, NIMG);
    hpss_kernel<<<grid, block>>>(S, out, n);
    (void)n_in; (void)out_size;
}

// round 4
// speedup vs baseline: 1.9030x; 1.9030x over previous
#include <cuda_runtime.h>

#define HH 1025
#define WW 1024
#define NIMG 4
#define RAD 15
#define KW 31

// scratch for harmonic (time-direction) medians
__device__ float g_harm[NIMG * HH * WW];

__device__ __forceinline__ void cas_asc(float &x, float &y) {
    float lo = fminf(x, y);
    float hi = fmaxf(x, y);
    x = lo; y = hi;
}

// bitonic sort of 32 floats ascending (a[31] may be +INF sentinel)
__device__ __forceinline__ void sort32(float a[32]) {
#pragma unroll
    for (int k = 2; k <= 32; k <<= 1)
#pragma unroll
        for (int j = k >> 1; j > 0; j >>= 1)
#pragma unroll
            for (int i = 0; i < 32; ++i) {
                int l = i ^ j;
                if (l > i) {
                    if ((i & k) == 0) cas_asc(a[i], a[l]);  // ascending run
                    else              cas_asc(a[l], a[i]);  // descending run
                }
            }
}

// sorted window a[0..30]; remove vold (present in window), insert vnew.
// delete: c[i] = (a[i] < vold) ? a[i] : a[i+1]   (monotone predicate; exact)
// insert: r[i] = max(c[i-1], min(c[i], vnew)),  c[-1]=-inf, c[30]=+inf
__device__ __forceinline__ void slide31(float a[32], float vold, float vnew) {
    float c_prev = (a[0] < vold) ? a[0] : a[1];
    a[0] = fminf(c_prev, vnew);
#pragma unroll
    for (int i = 1; i <= 29; ++i) {
        float ci = (a[i] < vold) ? a[i] : a[i + 1];
        float ri = fmaxf(c_prev, fminf(ci, vnew));
        a[i] = ri;
        c_prev = ci;
    }
    a[30] = fmaxf(c_prev, vnew);
}

// ───────────────────────── kernel A: harmonic (median along W) ─────────────
#define A_ROWS 128
#define A_COLS 64
#define A_TW (A_COLS + 2 * RAD)  // 94
#define A_STR 95                 // odd -> conflict-free

__global__ __launch_bounds__(128)
void hpss_harm(const float* __restrict__ S) {
    __shared__ float sm[A_ROWS * A_STR];
    const int img = blockIdx.z;
    const int h0 = blockIdx.y * A_ROWS;
    const int w0 = blockIdx.x * A_COLS;
    const float* __restrict__ Simg = S + (size_t)img * HH * WW;
    const int tid = threadIdx.x;

    for (int idx = tid; idx < A_ROWS * A_TW; idx += 128) {
        int r = idx / A_TW, c = idx - r * A_TW;
        int gh = h0 + r, gw = w0 - RAD + c;
        float v = 0.0f;
        if (gh < HH && gw >= 0 && gw < WW) v = Simg[gh * WW + gw];
        sm[r * A_STR + c] = v;
    }
    __syncthreads();

    if (h0 + tid < HH) {
        float* row = &sm[tid * A_STR];
        float a[32];
#pragma unroll
        for (int i = 0; i < 31; ++i) a[i] = row[i];
        a[31] = __int_as_float(0x7f800000);  // +INF
        sort32(a);
#pragma unroll 1
        for (int j = 0; j < A_COLS - 1; ++j) {
            float m = a[15];
            float vold = row[j];
            float vnew = row[j + KW];
            row[j] = m;           // col j is dead for this thread's window
            slide31(a, vold, vnew);
        }
        row[A_COLS - 1] = a[15];
    }
    __syncthreads();

    float* __restrict__ Himg = g_harm + (size_t)img * HH * WW;
    for (int idx = tid; idx < A_ROWS * A_COLS; idx += 128) {
        int r = idx >> 6, c = idx & 63;
        int gh = h0 + r;
        if (gh < HH) Himg[gh * WW + w0 + c] = sm[r * A_STR + c];
    }
}

// ─────────────── kernel B: percussive (median along H) + masks ─────────────
#define B_COLS 128
#define B_OUT 64
#define B_TH (B_OUT + 2 * RAD)  // 94
#define B_STR 95

__global__ __launch_bounds__(128)
void hpss_perc(const float* __restrict__ S, float* __restrict__ out, int n) {
    __shared__ float sm[B_COLS * B_STR];  // [col][row], transposed staging
    const int img = blockIdx.z;
    const int h0 = blockIdx.y * B_OUT;
    const int w0 = blockIdx.x * B_COLS;
    const float* __restrict__ Simg = S + (size_t)img * HH * WW;
    const float* __restrict__ Himg = g_harm + (size_t)img * HH * WW;
    const int tid = threadIdx.x;

    for (int idx = tid; idx < B_TH * B_COLS; idx += 128) {
        int r = idx >> 7, c = idx & 127;
        int gh = h0 - RAD + r;
        float v = 0.0f;
        if (gh >= 0 && gh < HH) v = Simg[gh * WW + w0 + c];
        sm[c * B_STR + r] = v;   // stride 95 across tid: conflict-free
    }
    __syncthreads();

    const int w = w0 + tid;
    float* col = &sm[tid * B_STR];
    float a[32];
#pragma unroll
    for (int i = 0; i < 31; ++i) a[i] = col[i];
    a[31] = __int_as_float(0x7f800000);
    sort32(a);

#pragma unroll 1
    for (int j = 0; j < B_OUT; ++j) {
        int hh = h0 + j;
        if (hh >= HH) break;                  // uniform across block
        float perc = a[15];
        float harm = Himg[hh * WW + w];       // coalesced
        float sv   = col[j + RAD];            // S[hh][w]
        // POWER=2, MARGIN=1: Z cancels -> masks = h2/(h2+p2), p2/(h2+p2)
        float h2 = harm * harm, p2 = perc * perc;
        float inv = __fdividef(1.0f, h2 + p2);
        size_t idx = (size_t)img * HH * WW + (size_t)hh * WW + w;
        out[idx]             = sv * (h2 * inv);
        out[(size_t)n + idx] = sv * (p2 * inv);
        if (j < B_OUT - 1) slide31(a, col[j], col[j + KW]);
    }
}

extern "C" void kernel_launch(void* const* d_in, const int* in_sizes, int n_in,
                              void* d_out, int out_size) {
    const float* S = (const float*)d_in[0];
    float* out = (float*)d_out;
    const int n = in_sizes[0];  // 4,198,400

    dim3 gA(WW / A_COLS, (HH + A_ROWS - 1) / A_ROWS, NIMG);  // 16 x 9 x 4
    hpss_harm<<<gA, 128>>>(S);
    dim3 gB(WW / B_COLS, (HH + B_OUT - 1) / B_OUT, NIMG);    // 8 x 17 x 4
    hpss_perc<<<gB, 128>>>(S, out, n);

    (void)n_in; (void)out_size;
}

// round 7
// speedup vs baseline: 2.1980x; 1.1550x over previous
#include <cuda_runtime.h>

#define HH 1025
#define WW 1024
#define NIMG 4
#define RAD 15
#define KW 31

// scratch for harmonic (time-direction) medians
__device__ float g_harm[NIMG * HH * WW];

__device__ __forceinline__ void cas_asc(float &x, float &y) {
    float lo = fminf(x, y);
    float hi = fmaxf(x, y);
    x = lo; y = hi;
}

// bitonic sort of 32 floats ascending (a[31] is +INF sentinel)
__device__ __forceinline__ void sort32(float a[32]) {
#pragma unroll
    for (int k = 2; k <= 32; k <<= 1)
#pragma unroll
        for (int j = k >> 1; j > 0; j >>= 1)
#pragma unroll
            for (int i = 0; i < 32; ++i) {
                int l = i ^ j;
                if (l > i) {
                    if ((i & k) == 0) cas_asc(a[i], a[l]);
                    else              cas_asc(a[l], a[i]);
                }
            }
}

// sorted window a[0..30]; remove vold (bitwise present), insert vnew.
__device__ __forceinline__ void slide31(float a[32], float vold, float vnew) {
    float c_prev = (a[0] < vold) ? a[0] : a[1];
    a[0] = fminf(c_prev, vnew);
#pragma unroll
    for (int i = 1; i <= 29; ++i) {
        float ci = (a[i] < vold) ? a[i] : a[i + 1];
        float ri = fmaxf(c_prev, fminf(ci, vnew));
        a[i] = ri;
        c_prev = ci;
    }
    a[30] = fmaxf(c_prev, vnew);
}

// ───────────────────────── kernel A: harmonic (median along W) ─────────────
#define A_ROWS 128
#define A_COLS 64
#define A_TW (A_COLS + 2 * RAD)  // 94
#define A_STR 95                 // odd -> conflict-free

__global__ __launch_bounds__(128)
void hpss_harm(const float* __restrict__ S) {
    __shared__ float sm[A_ROWS * A_STR];
    const int img = blockIdx.z;
    const int h0 = blockIdx.y * A_ROWS;
    const int w0 = blockIdx.x * A_COLS;
    const float* __restrict__ Simg = S + (size_t)img * HH * WW;
    const int tid = threadIdx.x;

    for (int idx = tid; idx < A_ROWS * A_TW; idx += 128) {
        int r = idx / A_TW, c = idx - r * A_TW;
        int gh = h0 + r, gw = w0 - RAD + c;
        float v = 0.0f;
        if (gh < HH && gw >= 0 && gw < WW) v = Simg[gh * WW + gw];
        sm[r * A_STR + c] = v;
    }
    __syncthreads();

    if (h0 + tid < HH) {
        float* row = &sm[tid * A_STR];
        float a[32];
#pragma unroll
        for (int i = 0; i < 31; ++i) a[i] = row[i];
        a[31] = __int_as_float(0x7f800000);  // +INF
        sort32(a);
#pragma unroll 1
        for (int j = 0; j < A_COLS - 1; ++j) {
            float m = a[15];
            float vold = row[j];
            float vnew = row[j + KW];
            row[j] = m;
            slide31(a, vold, vnew);
        }
        row[A_COLS - 1] = a[15];
    }
    __syncthreads();

    float* __restrict__ Himg = g_harm + (size_t)img * HH * WW;
    for (int idx = tid; idx < A_ROWS * A_COLS; idx += 128) {
        int r = idx >> 6, c = idx & 63;
        int gh = h0 + r;
        if (gh < HH) Himg[gh * WW + w0 + c] = sm[r * A_STR + c];
    }
}

// ─────────── kernel B: percussive (median along H) + masks, smem-free ──────
#define PJ 32   // outputs per thread along H

__global__ __launch_bounds__(128, 8)
void hpss_perc(const float* __restrict__ S, float* __restrict__ out, int n) {
    const int img = blockIdx.z;
    const int h0  = blockIdx.y * PJ;
    const int w   = blockIdx.x * 128 + threadIdx.x;   // coalesced across warp
    const float* __restrict__ colS = S + (size_t)img * HH * WW + w;
    const float* __restrict__ colH = g_harm + (size_t)img * HH * WW + w;
    float* __restrict__ outH = out + (size_t)img * HH * WW + w;
    float* __restrict__ outP = outH + (size_t)n;

    // init window rows [h0-15, h0+15], zero-padded
    float a[32];
#pragma unroll
    for (int i = 0; i < 31; ++i) {
        int gh = h0 - RAD + i;
        a[i] = (gh >= 0 && gh < HH) ? colS[(size_t)gh * WW] : 0.0f;
    }
    a[31] = __int_as_float(0x7f800000);  // +INF sentinel
    sort32(a);

#pragma unroll 2
    for (int j = 0; j < PJ; ++j) {
        const int hh = h0 + j;
        if (hh >= HH) break;                       // uniform across block
        const float perc = a[15];
        const float harm = colH[(size_t)hh * WW];  // coalesced, L2-resident
        const float sv   = colS[(size_t)hh * WW];  // L1 hit (streamed window)

        // POWER=2, MARGIN=1: Z cancels -> masks = h2/(h2+p2), p2/(h2+p2)
        const float h2 = harm * harm, p2 = perc * perc;
        const float inv = __fdividef(1.0f, h2 + p2);
        outH[(size_t)hh * WW] = sv * (h2 * inv);
        outP[(size_t)hh * WW] = sv * (p2 * inv);

        if (j != PJ - 1) {
            const int ho = hh - RAD;       // leaving row
            const int hn = hh + RAD + 1;   // entering row
            const float vold = (ho >= 0) ? colS[(size_t)ho * WW] : 0.0f;
            const float vnew = (hn < HH) ? colS[(size_t)hn * WW] : 0.0f;
            slide31(a, vold, vnew);
        }
    }
}

extern "C" void kernel_launch(void* const* d_in, const int* in_sizes, int n_in,
                              void* d_out, int out_size) {
    const float* S = (const float*)d_in[0];
    float* out = (float*)d_out;
    const int n = in_sizes[0];  // 4,198,400

    dim3 gA(WW / A_COLS, (HH + A_ROWS - 1) / A_ROWS, NIMG);  // 16 x 9 x 4
    hpss_harm<<<gA, 128>>>(S);
    dim3 gB(WW / 128, (HH + PJ - 1) / PJ, NIMG);             // 8 x 33 x 4
    hpss_perc<<<gB, 128>>>(S, out, n);

    (void)n_in; (void)out_size;
}